// round 5
// baseline (speedup 1.0000x reference)
#include <cuda_runtime.h>
#include <math.h>

#define T_LEN 128
#define B_DIM 128
#define I_DIM 128
#define H_DIM 512
#define W_WIN 16
#define G4H   2048   // 4*H
#define IH    640    // I+H

// ---------------- scratch (device globals; no allocation allowed) ----------
__device__ float g_h[2][B_DIM * H_DIM];
__device__ float g_c[B_DIM * H_DIM];
__device__ float g_V[W_WIN * B_DIM * H_DIM];
__device__ float g_attn[B_DIM * H_DIM];
__device__ float g_Q[B_DIM * H_DIM];

// ---------------- helpers ---------------------------------------------------
__device__ __forceinline__ unsigned smem_u32(const void* p) {
    return (unsigned)__cvta_generic_to_shared(p);
}
__device__ __forceinline__ void cp16(void* dst, const void* src) {
    asm volatile("cp.async.cg.shared.global [%0], [%1], 16;\n"
                 :: "r"(smem_u32(dst)), "l"(src));
}
__device__ __forceinline__ void cp_commit() {
    asm volatile("cp.async.commit_group;\n" ::: "memory");
}
__device__ __forceinline__ void cp_wait1() {
    asm volatile("cp.async.wait_group 1;\n" ::: "memory");
}
__device__ __forceinline__ void cp_wait0() {
    asm volatile("cp.async.wait_group 0;\n" ::: "memory");
}

// ---------------- init: h=0, c=0, V[w][b][:] = bv ---------------------------
__global__ void init_kernel(const float* __restrict__ bv) {
    int idx = blockIdx.x * blockDim.x + threadIdx.x;
    int stride = gridDim.x * blockDim.x;
    for (int i = idx; i < B_DIM * H_DIM; i += stride) {
        g_h[0][i] = 0.f;
        g_c[i] = 0.f;
    }
    for (int i = idx; i < W_WIN * B_DIM * H_DIM; i += stride) {
        g_V[i] = bv[i % H_DIM];
    }
}

// ---------------- KA: Q = [x_t|h] @ Wq + bq   AND   V[t%W] = c @ Wv + bv ----
// grid = 256 blocks x 128 threads.
// Blocks 0..127 : Q-GEMM (M=128, N=512, K=640)  tiles 16(M) x 32(N), TK=32
// Blocks 128..255: V-GEMM (M=128, N=512, K=512)
// A transposed to smem [k][row]; thread = 1 row x 4 contiguous cols.
__global__ __launch_bounds__(128) void ka_kernel(
    int t,
    const float* __restrict__ x,
    const float* __restrict__ Wq, const float* __restrict__ bq,
    const float* __restrict__ Wv, const float* __restrict__ bv)
{
    __shared__ float As[2][32][18];   // [stage][k][row(16)+pad]
    __shared__ float Ws[2][32][32];   // [stage][k][n]

    const int blk = blockIdx.x;
    const bool isQ = (blk < 128);
    const int bid = blk & 127;
    const int m0 = (bid >> 4) * 16;     // 8 M-tiles
    const int n0 = (bid & 15) * 32;     // 16 N-tiles

    const float* __restrict__ hin  = g_h[t & 1];
    const float* __restrict__ xt   = x + (size_t)t * B_DIM * I_DIM;
    const float* __restrict__ Wmat = isQ ? Wq : Wv;
    const int nt = isQ ? (IH / 32) : (H_DIM / 32);   // 20 or 16 k-tiles

    const int tid = threadIdx.x;
    const int tj4 = tid & 7;           // cols n0 + tj4*4 .. +3
    const int r   = tid >> 3;          // 0..15 row

    // A staging: thread owns row = tid&15, k-span (tid>>4)*4 .. +3
    const int arow = tid & 15;
    const int a4   = (tid >> 4) * 4;

    float ar[4];

    auto ldgA = [&](int it) {
        const int kk = it * 32;
        const float* p;
        if (isQ) {
            int gk = kk + a4;
            p = (gk < I_DIM) ? (xt + (size_t)(m0 + arow) * I_DIM + gk)
                             : (hin + (size_t)(m0 + arow) * H_DIM + (gk - I_DIM));
        } else {
            p = g_c + (size_t)(m0 + arow) * H_DIM + kk + a4;
        }
        *(float4*)ar = *(const float4*)p;
    };
    auto stsA = [&](int s) {
        #pragma unroll
        for (int i = 0; i < 4; i++) As[s][a4 + i][arow] = ar[i];
    };
    auto cpW = [&](int it, int s) {
        const int kk = it * 32;
        #pragma unroll
        for (int l = 0; l < 2; l++) {
            int id = tid + l * 128;
            int k = id >> 3, c4 = (id & 7) * 4;
            cp16(&Ws[s][k][c4], Wmat + (size_t)(kk + k) * H_DIM + n0 + c4);
        }
        cp_commit();
    };

    float acc[4] = {};

    ldgA(0); cpW(0, 0);
    for (int it = 0; it < nt; it++) {
        const int s = it & 1;
        stsA(s);
        if (it + 1 < nt) { ldgA(it + 1); cpW(it + 1, s ^ 1); cp_wait1(); }
        else             { cp_wait0(); }
        __syncthreads();

        #pragma unroll 8
        for (int k = 0; k < 32; k++) {
            float a = As[s][k][r];
            float4 w = *(const float4*)&Ws[s][k][tj4 * 4];
            acc[0] += a * w.x;  acc[1] += a * w.y;
            acc[2] += a * w.z;  acc[3] += a * w.w;
        }
        __syncthreads();
    }

    const float* bias = isQ ? bq : bv;
    float* outp = isQ ? g_Q : (g_V + (size_t)(t % W_WIN) * B_DIM * H_DIM);
    float4 bb = *(const float4*)(bias + n0 + tj4 * 4);
    float4 o;
    o.x = acc[0] + bb.x;  o.y = acc[1] + bb.y;
    o.z = acc[2] + bb.z;  o.w = acc[3] + bb.w;
    *(float4*)(outp + (size_t)(m0 + r) * H_DIM + n0 + tj4 * 4) = o;
}

// ---------------- KB: scores -> softmax -> attn -----------------------------
__global__ __launch_bounds__(128) void kb_kernel(int t) {
    const float inv_sqrt_dk = 0.044194173824159216f; // 1/sqrt(512)
    int b = blockIdx.x;
    int tid = threadIdx.x;
    __shared__ float sQ[H_DIM];
    __shared__ float sS[W_WIN];
    __shared__ float sP[W_WIN];

    for (int j = tid; j < H_DIM; j += 128) sQ[j] = g_Q[(size_t)b * H_DIM + j];
    __syncthreads();

    int nv = (t + 1 < W_WIN) ? (t + 1) : W_WIN;
    int warp = tid / 32, lane = tid % 32;
    for (int w = warp; w < nv; w += 4) {
        const float* Vp = g_V + (size_t)(w * B_DIM + b) * H_DIM;
        float p = 0.f;
        for (int j = lane; j < H_DIM; j += 32) p += sQ[j] * Vp[j];
        #pragma unroll
        for (int o = 16; o > 0; o >>= 1) p += __shfl_xor_sync(0xffffffffu, p, o);
        if (lane == 0) sS[w] = p * inv_sqrt_dk;
    }
    __syncthreads();
    if (tid == 0) {
        float m = sS[0];
        for (int w = 1; w < nv; w++) m = fmaxf(m, sS[w]);
        float sum = 0.f;
        for (int w = 0; w < nv; w++) { float e = expf(sS[w] - m); sP[w] = e; sum += e; }
        float inv = 1.f / sum;
        for (int w = 0; w < nv; w++) sP[w] *= inv;
    }
    __syncthreads();
    for (int j = tid; j < H_DIM; j += 128) {
        float a = 0.f;
        for (int w = 0; w < nv; w++)
            a += sP[w] * g_V[(size_t)(w * B_DIM + b) * H_DIM + j];
        g_attn[(size_t)b * H_DIM + j] = a;
    }
}

// ---------------- KC: fused cell GEMM + LSTM pointwise ----------------------
// preact = x_t@Wi + h@Wh + attn@Wa + biases (virtual K=1152).
// grid = 256 blocks (8 M-tiles x 32 j-tiles) x 128 threads.
// Tile: BM=16 rows x 16 j x 4 gates, TK=32.
// Thread: 2 rows x 1 gate x 4 j (gate recombine via smem epilogue).
__global__ __launch_bounds__(128) void kc_kernel(
    int t,
    const float* __restrict__ x,
    const float* __restrict__ Wi, const float* __restrict__ Wh,
    const float* __restrict__ Wa,
    const float* __restrict__ bi, const float* __restrict__ ba,
    float* __restrict__ out)
{
    __shared__ float As[2][32][18];   // [stage][k][row(16)+pad]
    __shared__ float Ws[2][32][64];   // [stage][k][g*16 + j]
    __shared__ float sP[4][16][16];   // [gate][row][j] preact exchange

    const int m0 = (blockIdx.x >> 5) * 16;  // 8 M-tiles
    const int j0 = (blockIdx.x & 31) * 16;  // 32 j-tiles

    const float* __restrict__ hin  = g_h[t & 1];
    float*       __restrict__ hout = g_h[(t + 1) & 1];
    const float* __restrict__ xt   = x + (size_t)t * B_DIM * I_DIM;

    const int tid = threadIdx.x;
    const int tj4 = tid & 3;           // j group: cols tj4*4 .. +3
    const int g   = (tid >> 2) & 3;    // gate
    const int rg  = tid >> 4;          // 0..7 -> rows rg*2, rg*2+1

    const int arow = tid & 15;
    const int a4   = (tid >> 4) * 4;

    float ar[4];

    // virtual K = 1152 : [0,128)=x/Wi  [128,640)=h/Wh  [640,1152)=attn/Wa
    auto ldgA = [&](int it) {
        const int kk = it * 32;
        const float* Aseg; int ldA, koff;
        if (kk < I_DIM)   { Aseg = xt;     ldA = I_DIM; koff = kk; }
        else if (kk < IH) { Aseg = hin;    ldA = H_DIM; koff = kk - I_DIM; }
        else              { Aseg = g_attn; ldA = H_DIM; koff = kk - IH; }
        *(float4*)ar = *(const float4*)(Aseg + (size_t)(m0 + arow) * ldA + koff + a4);
    };
    auto stsA = [&](int s) {
        #pragma unroll
        for (int i = 0; i < 4; i++) As[s][a4 + i][arow] = ar[i];
    };
    auto cpW = [&](int it, int s) {
        const int kk = it * 32;
        const float* Wseg; int koff;
        if (kk < I_DIM)   { Wseg = Wi; koff = kk; }
        else if (kk < IH) { Wseg = Wh; koff = kk - I_DIM; }
        else              { Wseg = Wa; koff = kk - IH; }
        #pragma unroll
        for (int l = 0; l < 4; l++) {
            int id = tid + l * 128;
            int k = id >> 4;
            int ch = id & 15;
            int gg = ch >> 2, c4 = (ch & 3) * 4;
            cp16(&Ws[s][k][gg * 16 + c4],
                 Wseg + (size_t)(koff + k) * G4H + gg * H_DIM + j0 + c4);
        }
        cp_commit();
    };

    float acc[2][4] = {};  // [row][j]

    const int nt = 36;     // 1152/32
    ldgA(0); cpW(0, 0);
    for (int it = 0; it < nt; it++) {
        const int s = it & 1;
        stsA(s);
        if (it + 1 < nt) { ldgA(it + 1); cpW(it + 1, s ^ 1); cp_wait1(); }
        else             { cp_wait0(); }
        __syncthreads();

        #pragma unroll 8
        for (int k = 0; k < 32; k++) {
            float2 a = *(const float2*)&As[s][k][rg * 2];
            float4 w = *(const float4*)&Ws[s][k][g * 16 + tj4 * 4];
            acc[0][0] += a.x * w.x;  acc[0][1] += a.x * w.y;
            acc[0][2] += a.x * w.z;  acc[0][3] += a.x * w.w;
            acc[1][0] += a.y * w.x;  acc[1][1] += a.y * w.y;
            acc[1][2] += a.y * w.z;  acc[1][3] += a.y * w.w;
        }
        __syncthreads();
    }

    // gate exchange
    *(float4*)&sP[g][rg * 2 + 0][tj4 * 4] = *(float4*)acc[0];
    *(float4*)&sP[g][rg * 2 + 1][tj4 * 4] = *(float4*)acc[1];
    __syncthreads();

    // pointwise: 2 cell elements per thread (same row, adjacent j)
    const int e   = tid * 2;
    const int row = e >> 4;
    const int jj  = e & 15;
    const int j   = j0 + jj;
    const int b   = m0 + row;

    float2 pi = { sP[0][row][jj], sP[0][row][jj + 1] };
    float2 pf = { sP[1][row][jj], sP[1][row][jj + 1] };
    float2 po = { sP[2][row][jj], sP[2][row][jj + 1] };
    float2 pg = { sP[3][row][jj], sP[3][row][jj + 1] };

    float2 bi0 = *(const float2*)(bi + j);
    float2 ba0 = *(const float2*)(ba + j);
    float2 bi1 = *(const float2*)(bi + H_DIM + j);
    float2 ba1 = *(const float2*)(ba + H_DIM + j);
    float2 bi2 = *(const float2*)(bi + 2 * H_DIM + j);
    float2 ba2 = *(const float2*)(ba + 2 * H_DIM + j);
    float2 bi3 = *(const float2*)(bi + 3 * H_DIM + j);
    float2 ba3 = *(const float2*)(ba + 3 * H_DIM + j);

    pi.x += bi0.x + ba0.x;  pi.y += bi0.y + ba0.y;
    pf.x += bi1.x + ba1.x;  pf.y += bi1.y + ba1.y;
    po.x += bi2.x + ba2.x;  po.y += bi2.y + ba2.y;
    pg.x += bi3.x + ba3.x;  pg.y += bi3.y + ba3.y;

    size_t idx = (size_t)b * H_DIM + j;
    float2 cold = *(const float2*)(g_c + idx);

    float igx = 1.f / (1.f + expf(-pi.x)), igy = 1.f / (1.f + expf(-pi.y));
    float fgx = 1.f / (1.f + expf(-pf.x)), fgy = 1.f / (1.f + expf(-pf.y));
    float ogx = 1.f / (1.f + expf(-po.x)), ogy = 1.f / (1.f + expf(-po.y));
    float ggx = tanhf(pg.x),               ggy = tanhf(pg.y);

    float2 cn, hn;
    cn.x = cold.x * fgx + igx * ggx;
    cn.y = cold.y * fgy + igy * ggy;
    hn.x = ogx * tanhf(cn.x);
    hn.y = ogy * tanhf(cn.y);

    *(float2*)(g_c + idx) = cn;
    *(float2*)(hout + idx) = hn;
    *(float2*)(out + (size_t)t * B_DIM * H_DIM + idx) = hn;
}

// ---------------- launcher --------------------------------------------------
extern "C" void kernel_launch(void* const* d_in, const int* in_sizes, int n_in,
                              void* d_out, int out_size) {
    const float* x  = (const float*)d_in[0];
    const float* Wi = (const float*)d_in[1];
    const float* bi = (const float*)d_in[2];
    const float* Wh = (const float*)d_in[3];
    const float* Wv = (const float*)d_in[4];
    const float* bv = (const float*)d_in[5];
    const float* Wq = (const float*)d_in[6];
    const float* bq = (const float*)d_in[7];
    const float* Wa = (const float*)d_in[8];
    const float* ba = (const float*)d_in[9];
    float* out = (float*)d_out;

    init_kernel<<<1024, 256>>>(bv);
    for (int t = 0; t < T_LEN; t++) {
        ka_kernel<<<256, 128>>>(t, x, Wq, bq, Wv, bv);
        kb_kernel<<<128, 128>>>(t);
        kc_kernel<<<256, 128>>>(t, x, Wi, Wh, Wa, bi, ba, out);
    }
}

// round 6
// speedup vs baseline: 1.4954x; 1.4954x over previous
#include <cuda_runtime.h>
#include <math.h>

#define T_LEN 128
#define B_DIM 128
#define I_DIM 128
#define H_DIM 512
#define W_WIN 16
#define G4H   2048   // 4*H
#define IH    640    // I+H
#define KC_K  1152   // I + H + H (virtual K for cell GEMM)

// ---------------- scratch (device globals; no allocation allowed) ----------
__device__ float g_h[2][B_DIM * H_DIM];
__device__ float g_c[B_DIM * H_DIM];
__device__ float g_V[W_WIN * B_DIM * H_DIM];
__device__ float g_attn[B_DIM * H_DIM];
__device__ float g_Q[B_DIM * H_DIM];

// transposed + tf32-split weights (computed once per call)
__device__ float g_Wc_hi[G4H * KC_K];   // [n=2048][k=1152]  (Wi|Wh|Wa)
__device__ float g_Wc_lo[G4H * KC_K];
__device__ float g_Wq_hi[H_DIM * IH];   // [n=512][k=640]
__device__ float g_Wq_lo[H_DIM * IH];
__device__ float g_Wv_hi[H_DIM * H_DIM];// [n=512][k=512]
__device__ float g_Wv_lo[H_DIM * H_DIM];

// ---------------- helpers ---------------------------------------------------
__device__ __forceinline__ unsigned smem_u32(const void* p) {
    return (unsigned)__cvta_generic_to_shared(p);
}
__device__ __forceinline__ void cp16(void* dst, const void* src) {
    asm volatile("cp.async.cg.shared.global [%0], [%1], 16;\n"
                 :: "r"(smem_u32(dst)), "l"(src));
}
__device__ __forceinline__ void cp_commit() {
    asm volatile("cp.async.commit_group;\n" ::: "memory");
}
__device__ __forceinline__ void cp_wait1() {
    asm volatile("cp.async.wait_group 1;\n" ::: "memory");
}
__device__ __forceinline__ void cp_wait0() {
    asm volatile("cp.async.wait_group 0;\n" ::: "memory");
}
__device__ __forceinline__ unsigned tf32u(float a) {
    unsigned r; asm("cvt.rna.tf32.f32 %0, %1;" : "=r"(r) : "f"(a)); return r;
}
// D += A(m16k8,row) * B(k8n8,col)   tf32
__device__ __forceinline__ void mma8(float* c, const unsigned* a,
                                     unsigned b0, unsigned b1) {
    asm("mma.sync.aligned.m16n8k8.row.col.f32.tf32.tf32.f32 "
        "{%0,%1,%2,%3},{%4,%5,%6,%7},{%8,%9},{%0,%1,%2,%3};"
        : "+f"(c[0]), "+f"(c[1]), "+f"(c[2]), "+f"(c[3])
        : "r"(a[0]), "r"(a[1]), "r"(a[2]), "r"(a[3]), "r"(b0), "r"(b1));
}

// ---------------- init: h=0, c=0, V[w][b][:] = bv ---------------------------
__global__ void init_kernel(const float* __restrict__ bv) {
    int idx = blockIdx.x * blockDim.x + threadIdx.x;
    int stride = gridDim.x * blockDim.x;
    for (int i = idx; i < B_DIM * H_DIM; i += stride) {
        g_h[0][i] = 0.f;
        g_c[i] = 0.f;
    }
    for (int i = idx; i < W_WIN * B_DIM * H_DIM; i += stride) {
        g_V[i] = bv[i % H_DIM];
    }
}

// ---------------- prep: transpose + tf32 hi/lo split ------------------------
__global__ void prep_wc(const float* __restrict__ Wi,
                        const float* __restrict__ Wh,
                        const float* __restrict__ Wa) {
    long total = (long)G4H * KC_K;
    long stride = (long)gridDim.x * blockDim.x;
    for (long i = (long)blockIdx.x * blockDim.x + threadIdx.x; i < total; i += stride) {
        int n = (int)(i / KC_K), k = (int)(i % KC_K);
        float w;
        if (k < I_DIM)   w = Wi[(size_t)k * G4H + n];
        else if (k < IH) w = Wh[(size_t)(k - I_DIM) * G4H + n];
        else             w = Wa[(size_t)(k - IH) * G4H + n];
        float hf = __uint_as_float(tf32u(w));
        g_Wc_hi[i] = hf;
        g_Wc_lo[i] = __uint_as_float(tf32u(w - hf));
    }
}
__global__ void prep_wqv(const float* __restrict__ Wq,
                         const float* __restrict__ Wv) {
    long totq = (long)H_DIM * IH;
    long totv = (long)H_DIM * H_DIM;
    long stride = (long)gridDim.x * blockDim.x;
    for (long i = (long)blockIdx.x * blockDim.x + threadIdx.x; i < totq + totv; i += stride) {
        if (i < totq) {
            int n = (int)(i / IH), k = (int)(i % IH);
            float w = Wq[(size_t)k * H_DIM + n];
            float hf = __uint_as_float(tf32u(w));
            g_Wq_hi[i] = hf;
            g_Wq_lo[i] = __uint_as_float(tf32u(w - hf));
        } else {
            long j = i - totq;
            int n = (int)(j / H_DIM), k = (int)(j % H_DIM);
            float w = Wv[(size_t)k * H_DIM + n];
            float hf = __uint_as_float(tf32u(w));
            g_Wv_hi[j] = hf;
            g_Wv_lo[j] = __uint_as_float(tf32u(w - hf));
        }
    }
}

// ---------------- KA: Q = [x_t|h] @ Wq + bq   AND   V[t%W] = c @ Wv + bv ----
// grid = 256 blocks x 128 threads (4 warps).
// Blocks 0..127 : Q-GEMM (M=128,N=512,K=640)  tile M16 x N32, warp m16n8
// Blocks 128..255: V-GEMM (M=128,N=512,K=512)
__global__ __launch_bounds__(128) void ka_kernel(
    int t,
    const float* __restrict__ x,
    const float* __restrict__ bq, const float* __restrict__ bv)
{
    __shared__ float As[2][16][36];
    __shared__ float Bh[2][32][36];
    __shared__ float Bl[2][32][36];

    const int blk = blockIdx.x;
    const bool isQ = (blk < 128);
    const int bid = blk & 127;
    const int m0 = (bid >> 4) * 16;     // 8 M-tiles
    const int n0 = (bid & 15) * 32;     // 16 N-tiles

    const float* __restrict__ hin = g_h[t & 1];
    const float* __restrict__ xt  = x + (size_t)t * B_DIM * I_DIM;
    const float* __restrict__ WH  = isQ ? g_Wq_hi : g_Wv_hi;
    const float* __restrict__ WL  = isQ ? g_Wq_lo : g_Wv_lo;
    const int Ktot = isQ ? IH : H_DIM;
    const int ldW  = Ktot;
    const int nt   = Ktot / 32;

    const int tid  = threadIdx.x;
    const int lane = tid & 31;
    const int warp = tid >> 5;
    const int g    = lane >> 2, tg = lane & 3;

    // stage loads
    const int ar = tid >> 3;            // 0..15 row (A)
    const int ac4 = (tid & 7) * 4;
    auto issue = [&](int it, int s) {
        const int kk = it * 32;
        // A: 16 rows x 32 k -> 1 cp16/thread
        {
            const float* p;
            if (isQ) {
                int gk = kk + ac4;
                p = (gk < I_DIM) ? (xt + (size_t)(m0 + ar) * I_DIM + gk)
                                 : (hin + (size_t)(m0 + ar) * H_DIM + (gk - I_DIM));
            } else {
                p = g_c + (size_t)(m0 + ar) * H_DIM + kk + ac4;
            }
            cp16(&As[s][ar][ac4], p);
        }
        // Bh/Bl: 32 n-rows x 32 k -> 2 cp16/thread each
        #pragma unroll
        for (int l = 0; l < 2; l++) {
            int id = tid + l * 128;
            int r = id >> 3, c4 = (id & 7) * 4;
            size_t off = (size_t)(n0 + r) * ldW + kk + c4;
            cp16(&Bh[s][r][c4], WH + off);
            cp16(&Bl[s][r][c4], WL + off);
        }
        cp_commit();
    };

    float acc[4] = {};

    issue(0, 0);
    for (int it = 0; it < nt; it++) {
        const int s = it & 1;
        if (it + 1 < nt) { issue(it + 1, s ^ 1); cp_wait1(); }
        else             { cp_wait0(); }
        __syncthreads();

        #pragma unroll
        for (int k8 = 0; k8 < 4; k8++) {
            const int k0 = k8 * 8;
            float a0 = As[s][g][k0 + tg];
            float a1 = As[s][g + 8][k0 + tg];
            float a2 = As[s][g][k0 + tg + 4];
            float a3 = As[s][g + 8][k0 + tg + 4];
            unsigned ah[4], al[4];
            ah[0] = tf32u(a0); al[0] = tf32u(a0 - __uint_as_float(ah[0]));
            ah[1] = tf32u(a1); al[1] = tf32u(a1 - __uint_as_float(ah[1]));
            ah[2] = tf32u(a2); al[2] = tf32u(a2 - __uint_as_float(ah[2]));
            ah[3] = tf32u(a3); al[3] = tf32u(a3 - __uint_as_float(ah[3]));

            int n = warp * 8 + g;
            unsigned bh0 = __float_as_uint(Bh[s][n][k0 + tg]);
            unsigned bh1 = __float_as_uint(Bh[s][n][k0 + tg + 4]);
            unsigned bl0 = __float_as_uint(Bl[s][n][k0 + tg]);
            unsigned bl1 = __float_as_uint(Bl[s][n][k0 + tg + 4]);
            mma8(acc, ah, bh0, bh1);
            mma8(acc, al, bh0, bh1);
            mma8(acc, ah, bl0, bl1);
        }
        __syncthreads();
    }

    const float* bias = isQ ? bq : bv;
    float* outp = isQ ? g_Q : (g_V + (size_t)(t % W_WIN) * B_DIM * H_DIM);
    int col = n0 + warp * 8 + 2 * tg;
    int r0 = m0 + g, r1 = m0 + g + 8;
    outp[(size_t)r0 * H_DIM + col]     = acc[0] + bias[col];
    outp[(size_t)r0 * H_DIM + col + 1] = acc[1] + bias[col + 1];
    outp[(size_t)r1 * H_DIM + col]     = acc[2] + bias[col];
    outp[(size_t)r1 * H_DIM + col + 1] = acc[3] + bias[col + 1];
}

// ---------------- KB: scores -> softmax -> attn -----------------------------
__global__ __launch_bounds__(128) void kb_kernel(int t) {
    const float inv_sqrt_dk = 0.044194173824159216f; // 1/sqrt(512)
    int b = blockIdx.x;
    int tid = threadIdx.x;
    __shared__ float sQ[H_DIM];
    __shared__ float sS[W_WIN];
    __shared__ float sP[W_WIN];

    for (int j = tid; j < H_DIM; j += 128) sQ[j] = g_Q[(size_t)b * H_DIM + j];
    __syncthreads();

    int nv = (t + 1 < W_WIN) ? (t + 1) : W_WIN;
    int warp = tid / 32, lane = tid % 32;
    for (int w = warp; w < nv; w += 4) {
        const float* Vp = g_V + (size_t)(w * B_DIM + b) * H_DIM;
        float p = 0.f;
        for (int j = lane; j < H_DIM; j += 32) p += sQ[j] * Vp[j];
        #pragma unroll
        for (int o = 16; o > 0; o >>= 1) p += __shfl_xor_sync(0xffffffffu, p, o);
        if (lane == 0) sS[w] = p * inv_sqrt_dk;
    }
    __syncthreads();
    if (tid == 0) {
        float m = sS[0];
        for (int w = 1; w < nv; w++) m = fmaxf(m, sS[w]);
        float sum = 0.f;
        for (int w = 0; w < nv; w++) { float e = expf(sS[w] - m); sP[w] = e; sum += e; }
        float inv = 1.f / sum;
        for (int w = 0; w < nv; w++) sP[w] *= inv;
    }
    __syncthreads();
    for (int j = tid; j < H_DIM; j += 128) {
        float a = 0.f;
        for (int w = 0; w < nv; w++)
            a += sP[w] * g_V[(size_t)(w * B_DIM + b) * H_DIM + j];
        g_attn[(size_t)b * H_DIM + j] = a;
    }
}

// ---------------- KC: fused cell GEMM (tf32 mma) + LSTM pointwise -----------
// preact = [x|h|attn] @ Wc + biases, virtual K=1152.
// grid = 256 blocks (4 M-tiles x 64 j-tiles) x 128 threads.
// Tile: M=32 rows x N=32 (4 gates x 8 j). Warp: m16 x n16 (2 n8 subtiles).
__global__ __launch_bounds__(128) void kc_kernel(
    int t,
    const float* __restrict__ x,
    const float* __restrict__ bi, const float* __restrict__ ba,
    float* __restrict__ out)
{
    __shared__ float As[2][32][36];
    __shared__ float Bh[2][32][36];
    __shared__ float Bl[2][32][36];
    __shared__ float sP[32][33];   // [row][col] preact exchange

    const int m0 = (blockIdx.x >> 6) * 32;  // 4 M-tiles
    const int j0 = (blockIdx.x & 63) * 8;   // 64 j-tiles

    const float* __restrict__ hin  = g_h[t & 1];
    float*       __restrict__ hout = g_h[(t + 1) & 1];
    const float* __restrict__ xt   = x + (size_t)t * B_DIM * I_DIM;

    const int tid  = threadIdx.x;
    const int lane = tid & 31;
    const int warp = tid >> 5;
    const int mrow = (warp & 1) * 16;
    const int ncol = (warp >> 1) * 16;
    const int g    = lane >> 2, tg = lane & 3;

    auto issue = [&](int it, int s) {
        const int kk = it * 32;
        // A: 32 rows x 32 k -> 2 cp16/thread
        #pragma unroll
        for (int l = 0; l < 2; l++) {
            int id = tid + l * 128;
            int r = id >> 3, c4 = (id & 7) * 4;
            const float* Aseg; int ldA, koff;
            if (kk < I_DIM)   { Aseg = xt;     ldA = I_DIM; koff = kk; }
            else if (kk < IH) { Aseg = hin;    ldA = H_DIM; koff = kk - I_DIM; }
            else              { Aseg = g_attn; ldA = H_DIM; koff = kk - IH; }
            cp16(&As[s][r][c4], Aseg + (size_t)(m0 + r) * ldA + koff + c4);
        }
        // Bh/Bl: 32 n-rows x 32 k (n row c -> gate c>>3, j j0+(c&7))
        #pragma unroll
        for (int l = 0; l < 2; l++) {
            int id = tid + l * 128;
            int r = id >> 3, c4 = (id & 7) * 4;
            int gn = (r >> 3) * H_DIM + j0 + (r & 7);
            size_t off = (size_t)gn * KC_K + kk + c4;
            cp16(&Bh[s][r][c4], g_Wc_hi + off);
            cp16(&Bl[s][r][c4], g_Wc_lo + off);
        }
        cp_commit();
    };

    float c0[4] = {}, c1[4] = {};

    const int nt = KC_K / 32;  // 36
    issue(0, 0);
    for (int it = 0; it < nt; it++) {
        const int s = it & 1;
        if (it + 1 < nt) { issue(it + 1, s ^ 1); cp_wait1(); }
        else             { cp_wait0(); }
        __syncthreads();

        #pragma unroll
        for (int k8 = 0; k8 < 4; k8++) {
            const int k0 = k8 * 8;
            float a0 = As[s][mrow + g][k0 + tg];
            float a1 = As[s][mrow + g + 8][k0 + tg];
            float a2 = As[s][mrow + g][k0 + tg + 4];
            float a3 = As[s][mrow + g + 8][k0 + tg + 4];
            unsigned ah[4], al[4];
            ah[0] = tf32u(a0); al[0] = tf32u(a0 - __uint_as_float(ah[0]));
            ah[1] = tf32u(a1); al[1] = tf32u(a1 - __uint_as_float(ah[1]));
            ah[2] = tf32u(a2); al[2] = tf32u(a2 - __uint_as_float(ah[2]));
            ah[3] = tf32u(a3); al[3] = tf32u(a3 - __uint_as_float(ah[3]));

            #pragma unroll
            for (int ns = 0; ns < 2; ns++) {
                int n = ncol + ns * 8 + g;
                unsigned bh0 = __float_as_uint(Bh[s][n][k0 + tg]);
                unsigned bh1 = __float_as_uint(Bh[s][n][k0 + tg + 4]);
                unsigned bl0 = __float_as_uint(Bl[s][n][k0 + tg]);
                unsigned bl1 = __float_as_uint(Bl[s][n][k0 + tg + 4]);
                float* cc = ns ? c1 : c0;
                mma8(cc, ah, bh0, bh1);
                mma8(cc, al, bh0, bh1);
                mma8(cc, ah, bl0, bl1);
            }
        }
        __syncthreads();
    }

    // exchange preact through smem
    {
        int col0 = ncol + 2 * tg;
        sP[mrow + g][col0]         = c0[0];
        sP[mrow + g][col0 + 1]     = c0[1];
        sP[mrow + g + 8][col0]     = c0[2];
        sP[mrow + g + 8][col0 + 1] = c0[3];
        sP[mrow + g][col0 + 8]         = c1[0];
        sP[mrow + g][col0 + 9]         = c1[1];
        sP[mrow + g + 8][col0 + 8]     = c1[2];
        sP[mrow + g + 8][col0 + 9]     = c1[3];
    }
    __syncthreads();

    // pointwise: 2 cells per thread (same row, jj and jj+1)
    const int cell = tid * 2;
    const int row = cell >> 3;
    const int jj  = cell & 7;
    const int j   = j0 + jj;
    const int b   = m0 + row;

    float2 pi = { sP[row][jj],      sP[row][jj + 1] };
    float2 pf = { sP[row][8 + jj],  sP[row][8 + jj + 1] };
    float2 po = { sP[row][16 + jj], sP[row][16 + jj + 1] };
    float2 pg = { sP[row][24 + jj], sP[row][24 + jj + 1] };

    float2 bi0 = *(const float2*)(bi + j);
    float2 ba0 = *(const float2*)(ba + j);
    float2 bi1 = *(const float2*)(bi + H_DIM + j);
    float2 ba1 = *(const float2*)(ba + H_DIM + j);
    float2 bi2 = *(const float2*)(bi + 2 * H_DIM + j);
    float2 ba2 = *(const float2*)(ba + 2 * H_DIM + j);
    float2 bi3 = *(const float2*)(bi + 3 * H_DIM + j);
    float2 ba3 = *(const float2*)(ba + 3 * H_DIM + j);

    pi.x += bi0.x + ba0.x;  pi.y += bi0.y + ba0.y;
    pf.x += bi1.x + ba1.x;  pf.y += bi1.y + ba1.y;
    po.x += bi2.x + ba2.x;  po.y += bi2.y + ba2.y;
    pg.x += bi3.x + ba3.x;  pg.y += bi3.y + ba3.y;

    size_t idx = (size_t)b * H_DIM + j;
    float2 cold = *(const float2*)(g_c + idx);

    float igx = 1.f / (1.f + expf(-pi.x)), igy = 1.f / (1.f + expf(-pi.y));
    float fgx = 1.f / (1.f + expf(-pf.x)), fgy = 1.f / (1.f + expf(-pf.y));
    float ogx = 1.f / (1.f + expf(-po.x)), ogy = 1.f / (1.f + expf(-po.y));
    float ggx = tanhf(pg.x),               ggy = tanhf(pg.y);

    float2 cn, hn;
    cn.x = cold.x * fgx + igx * ggx;
    cn.y = cold.y * fgy + igy * ggy;
    hn.x = ogx * tanhf(cn.x);
    hn.y = ogy * tanhf(cn.y);

    *(float2*)(g_c + idx) = cn;
    *(float2*)(hout + idx) = hn;
    *(float2*)(out + (size_t)t * B_DIM * H_DIM + idx) = hn;
}

// ---------------- launcher --------------------------------------------------
extern "C" void kernel_launch(void* const* d_in, const int* in_sizes, int n_in,
                              void* d_out, int out_size) {
    const float* x  = (const float*)d_in[0];
    const float* Wi = (const float*)d_in[1];
    const float* bi = (const float*)d_in[2];
    const float* Wh = (const float*)d_in[3];
    const float* Wv = (const float*)d_in[4];
    const float* bv = (const float*)d_in[5];
    const float* Wq = (const float*)d_in[6];
    const float* bq = (const float*)d_in[7];
    const float* Wa = (const float*)d_in[8];
    const float* ba = (const float*)d_in[9];
    float* out = (float*)d_out;

    init_kernel<<<1024, 256>>>(bv);
    prep_wc<<<2048, 256>>>(Wi, Wh, Wa);
    prep_wqv<<<1024, 256>>>(Wq, Wv);
    for (int t = 0; t < T_LEN; t++) {
        ka_kernel<<<256, 128>>>(t, x, bq, bv);
        kb_kernel<<<128, 128>>>(t);
        kc_kernel<<<256, 128>>>(t, x, bi, ba, out);
    }
}